// round 12
// baseline (speedup 1.0000x reference)
#include <cuda_runtime.h>

// LearnedEquivariance: per-sample 5x5 circular cross-correlation, applied twice.
// Channel-pair SIMD (fma.rn.f32x2 on interleaved float2 cells).
// R12: persistent CTA over 8 contiguous pair-planes, double smem buffers (A,B),
// next-plane fill prefetched into registers and overlapped with pass-2 compute.
// Kernel weights staged once per CTA (all 8 planes share one sample).

#define NT 224
#define SP 72                      // pair-cells per padded row (60 used)
#define BUF (60 * SP)              // 4320 float2 cells per buffer
#define SMEM_BYTES (2 * BUF * 8 + 128)

typedef unsigned long long u64;

__device__ __forceinline__ u64 pack2(float lo, float hi) {
    u64 r; asm("mov.b64 %0, {%1, %2};" : "=l"(r) : "f"(lo), "f"(hi)); return r;
}
__device__ __forceinline__ float2 unpack2(u64 v) {
    float2 r; asm("mov.b64 {%0, %1}, %2;" : "=f"(r.x), "=f"(r.y) : "l"(v)); return r;
}
__device__ __forceinline__ void fma2(u64 &acc, u64 a, u64 b) {
    asm("fma.rn.f32x2 %0, %1, %2, %0;" : "+l"(acc) : "l"(a), "l"(b));
}

// One circular 5x5 pass over a 2-wide x 7-tall tile of channel-pair outputs.
__device__ __forceinline__ void conv14(const float2* __restrict__ buf,
                                       const u64* __restrict__ KP,
                                       int R0, int j, u64 acc[7][2]) {
#pragma unroll
    for (int o = 0; o < 7; o++) { acc[o][0] = 0ull; acc[o][1] = 0ull; }
#pragma unroll
    for (int r = 0; r < 11; r++) {
        const ulonglong2* p =
            reinterpret_cast<const ulonglong2*>(buf + (R0 + r) * SP + j);
        ulonglong2 q0 = p[0], q1 = p[1], q2 = p[2];
        u64 P0 = q0.x, P1 = q0.y, P2 = q1.x, P3 = q1.y, P4 = q2.x, P5 = q2.y;
#pragma unroll
        for (int o = 0; o < 7; o++) {
            if (o > r || r > o + 4) continue;
            const int d = r - o;               // kernel row
            fma2(acc[o][0], P0, KP[d * 5 + 0]); fma2(acc[o][1], P1, KP[d * 5 + 0]);
            fma2(acc[o][0], P1, KP[d * 5 + 1]); fma2(acc[o][1], P2, KP[d * 5 + 1]);
            fma2(acc[o][0], P2, KP[d * 5 + 2]); fma2(acc[o][1], P3, KP[d * 5 + 2]);
            fma2(acc[o][0], P3, KP[d * 5 + 3]); fma2(acc[o][1], P4, KP[d * 5 + 3]);
            fma2(acc[o][0], P4, KP[d * 5 + 4]); fma2(acc[o][1], P5, KP[d * 5 + 4]);
        }
    }
}

__device__ __forceinline__ void stcell(float2* dst, u64 a, u64 b) {
    *reinterpret_cast<ulonglong2*>(dst) = make_ulonglong2(a, b);
}

// Halo coordinates for index idx in [0,464).
__device__ __forceinline__ void halo_coords(int idx, int &pr, int &pc) {
    if (idx < 120)      { pr = idx / 60;              pc = idx % 60; }
    else if (idx < 240) { pr = 58 + (idx - 120) / 60; pc = (idx - 120) % 60; }
    else { int t = idx - 240; pr = 2 + t / 4; int q = t % 4; pc = q < 2 ? q : 56 + q; }
}

__global__ __launch_bounds__(NT, 3)
void le_kernel(const float* __restrict__ x, const float* __restrict__ kern,
               const void* __restrict__ graw, float* __restrict__ out) {
    extern __shared__ float2 s2[];
    float2* A  = s2;                 // input / next-input buffer
    float2* Bm = s2 + BUF;           // mid (pass-1 result) buffer
    float* kw = (float*)(s2 + 2 * BUF);
    const int tid = threadIdx.x;
    const int ppBase = blockIdx.x * 8;   // 8 contiguous pair-planes per CTA
    const int b = ppBase >> 5;           // all 8 share this sample

    // Stage this sample's 5x5 kernel once (g dtype auto-detect).
    if (tid < 32) {
        const int* gi32 = (const int*)graw;
        bool oz = (gi32[2 * tid + 1] == 0) && (gi32[2 * tid + 65] == 0);
        unsigned m = __ballot_sync(0xffffffffu, oz);
        long long gv = (m == 0xffffffffu) ? ((const long long*)graw)[b]
                                          : (long long)gi32[b];
        int gi = (int)(((gv % 40) + 40) % 40);
        if (tid < 25) kw[tid] = kern[gi * 25 + tid];
    }

    // Fill A with first plane (direct).
    {
        const float* x0 = x + (long)ppBase * 2 * 3136;
        const float* x1 = x0 + 3136;
        for (int idx = tid; idx < 784; idx += NT) {
            float4 a = *reinterpret_cast<const float4*>(x0 + idx * 4);
            float4 c = *reinterpret_cast<const float4*>(x1 + idx * 4);
            int li = (idx * 4) / 56, lj = (idx * 4) % 56;
            float2* ad = A + (li + 2) * SP + lj + 2;
            stcell(ad,     pack2(a.x, c.x), pack2(a.y, c.y));
            stcell(ad + 2, pack2(a.z, c.z), pack2(a.w, c.w));
        }
        for (int idx = tid; idx < 464; idx += NT) {
            int pr, pc; halo_coords(idx, pr, pc);
            int li = (pr + 54) % 56, lj = (pc + 54) % 56;
            A[pr * SP + pc] = make_float2(x0[li * 56 + lj], x1[li * 56 + lj]);
        }
    }
    __syncthreads();

    u64 KP[25];
#pragma unroll
    for (int w = 0; w < 25; w++) { float v = kw[w]; KP[w] = pack2(v, v); }

    const int tr = tid / 28, tc = tid - tr * 28;
    const int R0 = tr * 7, j = tc * 2;

#pragma unroll 1
    for (int i = 0; i < 8; i++) {
        const int plane0 = (ppBase + i) * 2;
        u64 acc[7][2];

        // ---- pass 1: A -> Bm with circular halo replicas ----
        conv14(A, KP, R0, j, acc);
#pragma unroll
        for (int o = 0; o < 7; o++) {
            int ii = R0 + o;
            int pr = 2 + ii;
            stcell(Bm + pr * SP + 2 + j, acc[o][0], acc[o][1]);
            if (tc == 0)  stcell(Bm + pr * SP + 58, acc[o][0], acc[o][1]);
            if (tc == 27) stcell(Bm + pr * SP,      acc[o][0], acc[o][1]);
            if (ii < 2 || ii >= 54) {
                int pr2 = (ii < 2) ? pr + 56 : pr - 56;
                stcell(Bm + pr2 * SP + 2 + j, acc[o][0], acc[o][1]);
                if (tc == 0)  stcell(Bm + pr2 * SP + 58, acc[o][0], acc[o][1]);
                if (tc == 27) stcell(Bm + pr2 * SP,      acc[o][0], acc[o][1]);
            }
        }
        __syncthreads();    // Bm ready; all reads of A complete -> A reusable

        // ---- prefetch next plane's interior into registers (LDG now) ----
        const float* nx0 = x + (long)(plane0 + 2) * 3136;
        const float* nx1 = nx0 + 3136;
        float4 fa0, fa1, fa2, fa3, fc0, fc1, fc2, fc3;
        if (i < 7) {
            fa0 = *reinterpret_cast<const float4*>(nx0 + (tid          ) * 4);
            fa1 = *reinterpret_cast<const float4*>(nx0 + (tid +     NT ) * 4);
            fa2 = *reinterpret_cast<const float4*>(nx0 + (tid + 2 * NT ) * 4);
            fc0 = *reinterpret_cast<const float4*>(nx1 + (tid          ) * 4);
            fc1 = *reinterpret_cast<const float4*>(nx1 + (tid +     NT ) * 4);
            fc2 = *reinterpret_cast<const float4*>(nx1 + (tid + 2 * NT ) * 4);
            if (tid < 112) {
                fa3 = *reinterpret_cast<const float4*>(nx0 + (tid + 3 * NT) * 4);
                fc3 = *reinterpret_cast<const float4*>(nx1 + (tid + 3 * NT) * 4);
            }
        }

        // ---- pass 2: Bm -> gmem (overlaps the LDGs above) ----
        conv14(Bm, KP, R0, j, acc);
        float* o0 = out + (long)plane0 * 3136;
        float* o1 = o0 + 3136;
#pragma unroll
        for (int o = 0; o < 7; o++) {
            float2 a0 = unpack2(acc[o][0]), a1 = unpack2(acc[o][1]);
            int off = (R0 + o) * 56 + j;
            *reinterpret_cast<float2*>(o0 + off) = make_float2(a0.x, a1.x);
            *reinterpret_cast<float2*>(o1 + off) = make_float2(a0.y, a1.y);
        }

        // ---- commit prefetched interior + halo into A ----
        if (i < 7) {
#pragma unroll
            for (int k = 0; k < 4; k++) {
                int idx = tid + k * NT;
                if (k == 3 && tid >= 112) break;
                float4 a = (k == 0) ? fa0 : (k == 1) ? fa1 : (k == 2) ? fa2 : fa3;
                float4 c = (k == 0) ? fc0 : (k == 1) ? fc1 : (k == 2) ? fc2 : fc3;
                int li = (idx * 4) / 56, lj = (idx * 4) % 56;
                float2* ad = A + (li + 2) * SP + lj + 2;
                stcell(ad,     pack2(a.x, c.x), pack2(a.y, c.y));
                stcell(ad + 2, pack2(a.z, c.z), pack2(a.w, c.w));
            }
            for (int idx = tid; idx < 464; idx += NT) {
                int pr, pc; halo_coords(idx, pr, pc);
                int li = (pr + 54) % 56, lj = (pc + 54) % 56;
                A[pr * SP + pc] = make_float2(nx0[li * 56 + lj], nx1[li * 56 + lj]);
            }
        }
        __syncthreads();    // A ready for next p1; Bm reads done before next writes
    }
}

extern "C" void kernel_launch(void* const* d_in, const int* in_sizes, int n_in,
                              void* d_out, int out_size) {
    const float* x    = (const float*)d_in[0];  // [128,64,56,56] f32
    const float* kern = (const float*)d_in[1];  // [40,5,5] f32
    const void*  g    = d_in[2];                // [128] int32 or int64 (auto)
    float* out = (float*)d_out;

    cudaFuncSetAttribute(le_kernel, cudaFuncAttributeMaxDynamicSharedMemorySize,
                         SMEM_BYTES);
    // 4096 pair-planes = 512 CTAs x 8 contiguous planes (one sample per CTA)
    le_kernel<<<512, NT, SMEM_BYTES>>>(x, kern, g, out);
}

// round 13
// speedup vs baseline: 1.4981x; 1.4981x over previous
#include <cuda_runtime.h>

// LearnedEquivariance: per-sample 5x5 circular cross-correlation, applied twice.
// Channel-pair SIMD (fma.rn.f32x2 on interleaved float2 cells), single reused
// smem buffer, halo replication fused into pass-1 stores, 6 CTAs/SM, SP=72
// (conflict-free band stride). R13: revert R12 pipeline; streaming output stores.
// Sits at the measured FFMA2 rt=4 structural floor (~64.5 us @2.1GHz).

#define NT 224
#define SP 72                      // pair-cells per padded row (60 used)
#define BUF_CELLS (60 * SP)        // 4320 float2 cells
#define SMEM_BYTES (BUF_CELLS * 8 + 128)

typedef unsigned long long u64;

__device__ __forceinline__ u64 pack2(float lo, float hi) {
    u64 r; asm("mov.b64 %0, {%1, %2};" : "=l"(r) : "f"(lo), "f"(hi)); return r;
}
__device__ __forceinline__ float2 unpack2(u64 v) {
    float2 r; asm("mov.b64 {%0, %1}, %2;" : "=f"(r.x), "=f"(r.y) : "l"(v)); return r;
}
__device__ __forceinline__ void fma2(u64 &acc, u64 a, u64 b) {
    asm("fma.rn.f32x2 %0, %1, %2, %0;" : "+l"(acc) : "l"(a), "l"(b));
}
__device__ __forceinline__ void stg_cs_f2(float* p, float lo, float hi) {
    asm volatile("st.global.cs.v2.f32 [%0], {%1, %2};"
                 :: "l"(p), "f"(lo), "f"(hi) : "memory");
}

// One circular 5x5 pass over a 2-wide x 7-tall tile of channel-pair outputs.
// buf: padded pair-plane; padded (pr,pc) <-> logical (pr-2,pc-2).
__device__ __forceinline__ void conv14(const float2* __restrict__ buf,
                                       const u64* __restrict__ KP,
                                       int R0, int j, u64 acc[7][2]) {
#pragma unroll
    for (int o = 0; o < 7; o++) { acc[o][0] = 0ull; acc[o][1] = 0ull; }
#pragma unroll
    for (int r = 0; r < 11; r++) {
        const ulonglong2* p =
            reinterpret_cast<const ulonglong2*>(buf + (R0 + r) * SP + j);
        ulonglong2 q0 = p[0], q1 = p[1], q2 = p[2];
        u64 P0 = q0.x, P1 = q0.y, P2 = q1.x, P3 = q1.y, P4 = q2.x, P5 = q2.y;
#pragma unroll
        for (int o = 0; o < 7; o++) {
            if (o > r || r > o + 4) continue;
            const int d = r - o;               // kernel row
            fma2(acc[o][0], P0, KP[d * 5 + 0]); fma2(acc[o][1], P1, KP[d * 5 + 0]);
            fma2(acc[o][0], P1, KP[d * 5 + 1]); fma2(acc[o][1], P2, KP[d * 5 + 1]);
            fma2(acc[o][0], P2, KP[d * 5 + 2]); fma2(acc[o][1], P3, KP[d * 5 + 2]);
            fma2(acc[o][0], P3, KP[d * 5 + 3]); fma2(acc[o][1], P4, KP[d * 5 + 3]);
            fma2(acc[o][0], P4, KP[d * 5 + 4]); fma2(acc[o][1], P5, KP[d * 5 + 4]);
        }
    }
}

__device__ __forceinline__ void stcell(float2* dst, u64 a, u64 b) {
    *reinterpret_cast<ulonglong2*>(dst) = make_ulonglong2(a, b);
}

__global__ __launch_bounds__(NT, 6)
void le_kernel(const float* __restrict__ x, const float* __restrict__ kern,
               const void* __restrict__ graw, float* __restrict__ out) {
    extern __shared__ float2 s2[];          // one 60x72 padded pair-plane
    const int tid = threadIdx.x;
    const int plane0 = blockIdx.x * 2;      // channel pair within one sample
    const int b = plane0 >> 6;
    float* kw = (float*)(s2 + BUF_CELLS);

    // Warp 0: g dtype detect (int64 -> odd int32 words of first 512B all zero),
    // then stage this sample's 5x5 kernel.
    if (tid < 32) {
        const int* gi32 = (const int*)graw;
        bool oz = (gi32[2 * tid + 1] == 0) && (gi32[2 * tid + 65] == 0);
        unsigned m = __ballot_sync(0xffffffffu, oz);
        long long gv = (m == 0xffffffffu) ? ((const long long*)graw)[b]
                                          : (long long)gi32[b];
        int gi = (int)(((gv % 40) + 40) % 40);
        if (tid < 25) kw[tid] = kern[gi * 25 + tid];
    }

    const float* x0 = x + (long)plane0 * 3136;
    const float* x1 = x0 + 3136;

    // Interior fill: coalesced float4 loads, 4 cells per iteration.
    for (int idx = tid; idx < 784; idx += NT) {
        float4 a = *reinterpret_cast<const float4*>(x0 + idx * 4);
        float4 c = *reinterpret_cast<const float4*>(x1 + idx * 4);
        int li = (idx * 4) / 56, lj = (idx * 4) % 56;
        float2* ad = s2 + (li + 2) * SP + lj + 2;
        stcell(ad,     pack2(a.x, c.x), pack2(a.y, c.y));
        stcell(ad + 2, pack2(a.z, c.z), pack2(a.w, c.w));
    }
    // Halo fill: 464 wrap cells straight from gmem.
    // rows 0,1 (120) + rows 58,59 (120) + side cols pc in {0,1,58,59} for pr 2..57.
    for (int idx = tid; idx < 464; idx += NT) {
        int pr, pc;
        if (idx < 120)      { pr = idx / 60;              pc = idx % 60; }
        else if (idx < 240) { pr = 58 + (idx - 120) / 60; pc = (idx - 120) % 60; }
        else { int t = idx - 240; pr = 2 + t / 4; int q = t % 4; pc = q < 2 ? q : 56 + q; }
        int li = (pr + 54) % 56, lj = (pc + 54) % 56;
        s2[pr * SP + pc] = make_float2(x0[li * 56 + lj], x1[li * 56 + lj]);
    }
    __syncthreads();

    u64 KP[25];
#pragma unroll
    for (int w = 0; w < 25; w++) { float v = kw[w]; KP[w] = pack2(v, v); }

    const int tr = tid / 28, tc = tid - tr * 28;
    const int R0 = tr * 7, j = tc * 2;

    // ---- pass 1: read whole buffer into 14 reg accumulators ----
    u64 acc[7][2];
    conv14(s2, KP, R0, j, acc);
    __syncthreads();   // all pass-1 reads complete before in-place overwrite

    // ---- store pass-1 results in place, with circular halo replicas ----
#pragma unroll
    for (int o = 0; o < 7; o++) {
        int i = R0 + o;
        int pr = 2 + i;
        stcell(s2 + pr * SP + 2 + j, acc[o][0], acc[o][1]);
        if (tc == 0)  stcell(s2 + pr * SP + 58, acc[o][0], acc[o][1]);
        if (tc == 27) stcell(s2 + pr * SP,      acc[o][0], acc[o][1]);
        if (i < 2 || i >= 54) {
            int pr2 = (i < 2) ? pr + 56 : pr - 56;
            stcell(s2 + pr2 * SP + 2 + j, acc[o][0], acc[o][1]);
            if (tc == 0)  stcell(s2 + pr2 * SP + 58, acc[o][0], acc[o][1]);
            if (tc == 27) stcell(s2 + pr2 * SP,      acc[o][0], acc[o][1]);
        }
    }
    __syncthreads();

    // ---- pass 2: buffer -> gmem (streaming stores, write-once data) ----
    conv14(s2, KP, R0, j, acc);
    float* o0 = out + (long)plane0 * 3136;
    float* o1 = o0 + 3136;
#pragma unroll
    for (int o = 0; o < 7; o++) {
        float2 a0 = unpack2(acc[o][0]), a1 = unpack2(acc[o][1]);
        int off = (R0 + o) * 56 + j;
        stg_cs_f2(o0 + off, a0.x, a1.x);
        stg_cs_f2(o1 + off, a0.y, a1.y);
    }
}

extern "C" void kernel_launch(void* const* d_in, const int* in_sizes, int n_in,
                              void* d_out, int out_size) {
    const float* x    = (const float*)d_in[0];  // [128,64,56,56] f32
    const float* kern = (const float*)d_in[1];  // [40,5,5] f32
    const void*  g    = d_in[2];                // [128] int32 or int64 (auto)
    float* out = (float*)d_out;

    cudaFuncSetAttribute(le_kernel, cudaFuncAttributeMaxDynamicSharedMemorySize,
                         SMEM_BYTES);
    le_kernel<<<4096, NT, SMEM_BYTES>>>(x, kern, g, out);  // one pair-plane/block
}